// round 5
// baseline (speedup 1.0000x reference)
#include <cuda_runtime.h>

// ---------------------------------------------------------------------------
// Fused NeRF MLP evaluation, fp32, f32x2-packed FFMA.
// One CTA = 128 points. Activations live in SMEM feature-major: act[f][r],
// f in [0,328), r in [0,128). Concats become contiguous column ranges:
//   pe_x    -> cols [0,63)
//   features-> cols [63,319)        (in-place updated every layer)
//   pe_d    -> cols [24,63)         (written after g2 layer0 consumed pe_x)
// Columns [319,328) stay zero so K-tail reads (K=63/319/295, tiles of 8)
// multiply garbage-free zeros.
// ---------------------------------------------------------------------------

#define TPB    512
#define MROWS  128
#define AST    128          // act row stride (floats)
#define ACOLS  328
#define WS_OFF  (ACOLS*AST)          // 41984 floats
#define BS_OFF  (WS_OFF + 4096)      // Ws: double-buffered 8x256
#define DIR_OFF (BS_OFF + 256)
#define SMEM_FLOATS (DIR_OFF + 384)
#define SMEM_BYTES  (SMEM_FLOATS * 4)   // 186,880 B

typedef unsigned long long ull;

__device__ __forceinline__ ull dup2(float v) {
    ull r; asm("mov.b64 %0, {%1, %1};" : "=l"(r) : "f"(v)); return r;
}
__device__ __forceinline__ void ffma2(ull &d, ull a, ull b) {
    asm("fma.rn.f32x2 %0, %1, %2, %0;" : "+l"(d) : "l"(a), "l"(b));
}
__device__ __forceinline__ float lo32(ull v) { return __uint_as_float((unsigned)v); }
__device__ __forceinline__ float hi32(ull v) { return __uint_as_float((unsigned)(v >> 32)); }

// One dense layer: out[128,256] = act(in cols) @ W[K,256] + b, optional ReLU,
// written in-place (feature-major) at column outoff. Double-buffered 8x256
// weight tiles. 512 threads: warp -> 8 rows, lane -> cols {4*lane..+3} and
// {128+4*lane..+3}; accumulators are f32x2 over row pairs.
__device__ __noinline__ void dense_layer(float* __restrict__ act,
                                         float* __restrict__ Ws,
                                         float* __restrict__ bs,
                                         const float* __restrict__ Wg,
                                         const float* __restrict__ bg,
                                         int K, int inoff, int outoff, int do_relu)
{
    const int tid  = threadIdx.x;
    const int lane = tid & 31;
    const int rw   = (tid >> 5) * 8;       // warp -> row base
    const int lk   = tid >> 6;             // 0..7 : k-row within weight tile
    const int ln   = (tid & 63) << 2;      // 0..252 : n-col within weight tile

    if (tid < 64) ((float4*)bs)[tid] = ((const float4*)bg)[tid];

    float4 wreg;
    {
        int kk = lk;
        if (kk < K) wreg = *(const float4*)(Wg + (size_t)kk * 256 + ln);
        else        wreg = make_float4(0.f, 0.f, 0.f, 0.f);
    }
    __syncthreads();   // prev-layer stores + bias visible; Ws buffers free

    ull acc[8][4];
    #pragma unroll
    for (int c = 0; c < 8; ++c) {
        int n = (c < 4) ? (lane * 4 + c) : (128 + lane * 4 + (c - 4));
        ull d = dup2(bs[n]);
        #pragma unroll
        for (int rp = 0; rp < 4; ++rp) acc[c][rp] = d;
    }

    *(float4*)(Ws + (size_t)lk * 256 + ln) = wreg;
    __syncthreads();

    const int nt = (K + 7) >> 3;
    for (int t = 0; t < nt; ++t) {
        if (t + 1 < nt) {
            int kk = (t + 1) * 8 + lk;
            if (kk < K) wreg = *(const float4*)(Wg + (size_t)kk * 256 + ln);
            else        wreg = make_float4(0.f, 0.f, 0.f, 0.f);
        }
        const float* wsb = Ws + (t & 1) * 2048;
        const int kbase = inoff + t * 8;
        #pragma unroll
        for (int k = 0; k < 8; ++k) {
            const float* ap = act + (size_t)(kbase + k) * AST + rw;   // warp-uniform: broadcast
            ulonglong2 aA = *(const ulonglong2*)ap;
            ulonglong2 aB = *(const ulonglong2*)(ap + 4);
            ull a2[4] = { aA.x, aA.y, aB.x, aB.y };
            const float* wp = wsb + k * 256 + (lane << 2);            // 16B/lane: conflict-free
            float4 b0 = *(const float4*)wp;
            float4 b1 = *(const float4*)(wp + 128);
            ull bd[8] = { dup2(b0.x), dup2(b0.y), dup2(b0.z), dup2(b0.w),
                          dup2(b1.x), dup2(b1.y), dup2(b1.z), dup2(b1.w) };
            #pragma unroll
            for (int c = 0; c < 8; ++c)
                #pragma unroll
                for (int rp = 0; rp < 4; ++rp)
                    ffma2(acc[c][rp], a2[rp], bd[c]);
        }
        __syncthreads();   // all reads of input cols + this buffer done
        if (t + 1 < nt) {
            *(float4*)(Ws + ((t + 1) & 1) * 2048 + (size_t)lk * 256 + ln) = wreg;
            __syncthreads();
        }
    }

    // Epilogue: ReLU + in-place store (safe: all input reads completed at the
    // unconditional sync of the final tile).
    #pragma unroll
    for (int c = 0; c < 8; ++c) {
        int n = (c < 4) ? (lane * 4 + c) : (128 + lane * 4 + (c - 4));
        float* op = act + (size_t)(outoff + n) * AST + rw;
        #pragma unroll
        for (int rp = 0; rp < 4; ++rp) {
            float lo = lo32(acc[c][rp]);
            float hi = hi32(acc[c][rp]);
            if (do_relu) { lo = fmaxf(lo, 0.f); hi = fmaxf(hi, 0.f); }
            op[2 * rp]     = lo;
            op[2 * rp + 1] = hi;
        }
    }
    // no trailing sync: next layer's entry sync covers visibility
}

__global__ void __launch_bounds__(TPB, 1) nerf_kernel(
    const float* __restrict__ x, const float* __restrict__ dirg,
    const float* g1_0_W, const float* g1_0_b,
    const float* g1_1_W, const float* g1_1_b,
    const float* g1_2_W, const float* g1_2_b,
    const float* g1_3_W, const float* g1_3_b,
    const float* g1_4_W, const float* g1_4_b,
    const float* g2_0_W, const float* g2_0_b,
    const float* g2_1_W, const float* g2_1_b,
    const float* g2_2_W, const float* g2_2_b,
    const float* c_0_W,  const float* c_0_b,
    const float* c_1_W,  const float* c_1_b,
    const float* sig_W,  const float* sig_b,
    float* __restrict__ out)
{
    extern __shared__ float smem[];
    float* act  = smem;
    float* Ws   = smem + WS_OFF;
    float* bs   = smem + BS_OFF;
    float* dirb = smem + DIR_OFF;

    const int tid  = threadIdx.x;
    const int row0 = blockIdx.x * MROWS;
    const int r = tid >> 2, p = tid & 3;

    // Zero the activation buffer (tail columns + first-layer tail reads rely on it)
    for (int i = tid; i < ACOLS * AST; i += TPB) act[i] = 0.f;

    // Load x / direction rows (4 threads per row)
    const float* xr = x + (size_t)(row0 + r) * 3;
    float xv0 = xr[0], xv1 = xr[1], xv2 = xr[2];
    if (p == 1) {
        const float* dr = dirg + (size_t)(row0 + r) * 3;
        dirb[r] = dr[0]; dirb[128 + r] = dr[1]; dirb[256 + r] = dr[2];
    }
    __syncthreads();   // zeros visible before PE writes

    // pe_x -> cols [0,63): [x, sin/cos interleaved per freq]
    if (p == 0) {
        act[0 * AST + r] = xv0; act[1 * AST + r] = xv1; act[2 * AST + r] = xv2;
    }
    for (int l = p; l < 10; l += 4) {
        float f = (float)(1 << l);
        float s, c;
        sincosf(xv0 * f, &s, &c); act[(3 + 6 * l + 0) * AST + r] = s; act[(6 + 6 * l + 0) * AST + r] = c;
        sincosf(xv1 * f, &s, &c); act[(3 + 6 * l + 1) * AST + r] = s; act[(6 + 6 * l + 1) * AST + r] = c;
        sincosf(xv2 * f, &s, &c); act[(3 + 6 * l + 2) * AST + r] = s; act[(6 + 6 * l + 2) * AST + r] = c;
    }

    // g1: 63->256, 256->256 x3 (ReLU), 256->256 (no ReLU)
    dense_layer(act, Ws, bs, g1_0_W, g1_0_b,  63,  0, 63, 1);
    dense_layer(act, Ws, bs, g1_1_W, g1_1_b, 256, 63, 63, 1);
    dense_layer(act, Ws, bs, g1_2_W, g1_2_b, 256, 63, 63, 1);
    dense_layer(act, Ws, bs, g1_3_W, g1_3_b, 256, 63, 63, 1);
    dense_layer(act, Ws, bs, g1_4_W, g1_4_b, 256, 63, 63, 0);

    // g2 layer0 reads cols [0,319) = [pe_x | features1]
    dense_layer(act, Ws, bs, g2_0_W, g2_0_b, 319,  0, 63, 1);

    // pe_d -> cols [24,63) (pe_x no longer needed). Safe: g2_0's final
    // internal sync ordered all reads of cols [0,63) before we get here.
    {
        float d0 = dirb[r], d1 = dirb[128 + r], d2 = dirb[256 + r];
        if (p == 0) {
            act[(24 + 0) * AST + r] = d0; act[(24 + 1) * AST + r] = d1; act[(24 + 2) * AST + r] = d2;
        }
        for (int l = p; l < 6; l += 4) {
            float f = (float)(1 << l);
            float s, c;
            sincosf(d0 * f, &s, &c); act[(27 + 6 * l + 0) * AST + r] = s; act[(30 + 6 * l + 0) * AST + r] = c;
            sincosf(d1 * f, &s, &c); act[(27 + 6 * l + 1) * AST + r] = s; act[(30 + 6 * l + 1) * AST + r] = c;
            sincosf(d2 * f, &s, &c); act[(27 + 6 * l + 2) * AST + r] = s; act[(30 + 6 * l + 2) * AST + r] = c;
        }
    }

    dense_layer(act, Ws, bs, g2_1_W, g2_1_b, 256, 63, 63, 1);
    dense_layer(act, Ws, bs, g2_2_W, g2_2_b, 256, 63, 63, 0);   // features2
    __syncthreads();

    // sigma = features2 @ sig_W + sig_b  (4 threads/row, shuffle reduce)
    float sigma_r;
    {
        float s = 0.f;
        #pragma unroll 8
        for (int kk = 0; kk < 64; ++kk) {
            int k = p * 64 + kk;
            s += act[(63 + k) * AST + r] * sig_W[k];
        }
        s += __shfl_xor_sync(0xffffffffu, s, 1);
        s += __shfl_xor_sync(0xffffffffu, s, 2);
        sigma_r = s + sig_b[0];
    }

    // color layer0 reads cols [24,319) = [pe_d | features2]; its entry sync
    // orders all sigma reads of features2 before the in-place overwrite.
    dense_layer(act, Ws, bs, c_0_W, c_0_b, 295, 24, 63, 1);
    __syncthreads();

    // color layer1: 256->3 (no ReLU) + fused output write [rgb, sigma]
    {
        float o0 = 0.f, o1 = 0.f, o2 = 0.f;
        #pragma unroll 8
        for (int kk = 0; kk < 64; ++kk) {
            int k = p * 64 + kk;
            float a = act[(63 + k) * AST + r];
            o0 += a * c_1_W[k * 3 + 0];
            o1 += a * c_1_W[k * 3 + 1];
            o2 += a * c_1_W[k * 3 + 2];
        }
        o0 += __shfl_xor_sync(0xffffffffu, o0, 1);
        o0 += __shfl_xor_sync(0xffffffffu, o0, 2);
        o1 += __shfl_xor_sync(0xffffffffu, o1, 1);
        o1 += __shfl_xor_sync(0xffffffffu, o1, 2);
        o2 += __shfl_xor_sync(0xffffffffu, o2, 1);
        o2 += __shfl_xor_sync(0xffffffffu, o2, 2);
        if (p == 0) {
            float4 o = make_float4(o0 + c_1_b[0], o1 + c_1_b[1], o2 + c_1_b[2], sigma_r);
            *(float4*)(out + (size_t)(row0 + r) * 4) = o;
        }
    }
}

extern "C" void kernel_launch(void* const* d_in, const int* in_sizes, int n_in,
                              void* d_out, int out_size)
{
    const float* x     = (const float*)d_in[0];
    const float* dirg  = (const float*)d_in[1];
    const float* g1_0_W = (const float*)d_in[2];  const float* g1_0_b = (const float*)d_in[3];
    const float* g1_1_W = (const float*)d_in[4];  const float* g1_1_b = (const float*)d_in[5];
    const float* g1_2_W = (const float*)d_in[6];  const float* g1_2_b = (const float*)d_in[7];
    const float* g1_3_W = (const float*)d_in[8];  const float* g1_3_b = (const float*)d_in[9];
    const float* g1_4_W = (const float*)d_in[10]; const float* g1_4_b = (const float*)d_in[11];
    const float* g2_0_W = (const float*)d_in[12]; const float* g2_0_b = (const float*)d_in[13];
    const float* g2_1_W = (const float*)d_in[14]; const float* g2_1_b = (const float*)d_in[15];
    const float* g2_2_W = (const float*)d_in[16]; const float* g2_2_b = (const float*)d_in[17];
    const float* c_0_W  = (const float*)d_in[18]; const float* c_0_b  = (const float*)d_in[19];
    const float* c_1_W  = (const float*)d_in[20]; const float* c_1_b  = (const float*)d_in[21];
    const float* sig_W  = (const float*)d_in[22]; const float* sig_b  = (const float*)d_in[23];
    float* out = (float*)d_out;

    const int N = in_sizes[0] / 3;           // 262144
    const int nblocks = N / MROWS;           // 2048

    cudaFuncSetAttribute(nerf_kernel, cudaFuncAttributeMaxDynamicSharedMemorySize, SMEM_BYTES);

    nerf_kernel<<<nblocks, TPB, SMEM_BYTES>>>(
        x, dirg,
        g1_0_W, g1_0_b, g1_1_W, g1_1_b, g1_2_W, g1_2_b, g1_3_W, g1_3_b, g1_4_W, g1_4_b,
        g2_0_W, g2_0_b, g2_1_W, g2_1_b, g2_2_W, g2_2_b,
        c_0_W, c_0_b, c_1_W, c_1_b,
        sig_W, sig_b,
        out);
}